// round 5
// baseline (speedup 1.0000x reference)
#include <cuda_runtime.h>
#include <cstdint>

// Problem constants
#define BATCH   512
#define OUTF    1024
#define KDIM    128      // NUM_BLOCKS * LATTICE_DIM
#define NIDX    256      // MAX_INDICES

// Tiling for main kernel
#define NSEG    8        // k-segments (grid.y)
#define KSEG    16       // k per segment
#define KCH     2        // k per staging chunk (per buffer)
#define NCH     (KSEG / KCH)       // 8 chunks
#define BT      32       // b per CTA (== warp width, conflict-free requirement)
#define MTHREADS 1024    // 32 warps: warp w owns o = w*32 .. w*32+31
#define BUF_F   (KCH * 32 * 256)   // floats per buffer = 16384 (64 KB)
#define BUF_BYTES (BUF_F * 4)

// Per-segment partials, [seg][o][b] (b contiguous): 16 MB
__device__ float g_part[NSEG][OUTF][BATCH];

__device__ __forceinline__ void cpa4(uint32_t dst, const float* src) {
    asm volatile("cp.async.ca.shared.global [%0], [%1], 4;" :: "r"(dst), "l"(src));
}
__device__ __forceinline__ void cp_commit() {
    asm volatile("cp.async.commit_group;" ::: "memory");
}
__device__ __forceinline__ void cp_wait0() {
    asm volatile("cp.async.wait_group 0;" ::: "memory");
}

// ---------------- main kernel: cp.async double-buffered conflict-free smem gather ----------------
// CTA (btile, seg): b in [btile*32, btile*32+32), k in [seg*16, seg*16+16), all 1024 o.
// smem: S[buf][kk][b][ j ^ b ]; gather with lane==b is bank-conflict-free.
__global__ __launch_bounds__(MTHREADS, 1) void lut_main(
    const int*   __restrict__ inp,   // [BATCH, KDIM] int32
    const int*   __restrict__ wgt,   // [OUTF, KDIM]  int32
    const float* __restrict__ lut)   // [256, 256]
{
    extern __shared__ float S[];     // 2 * BUF_F floats = 128 KB

    const int btile = blockIdx.x;    // 0..15
    const int seg   = blockIdx.y;    // 0..7
    const int tid   = threadIdx.x;
    const int wid   = tid >> 5;
    const int lane  = tid & 31;
    const int obase = wid * 32;

    // ---- fused pack: this lane's 16 weight indices (o = obase+lane) as 4 byte-words ----
    const int* wp = wgt + (obase + lane) * KDIM + seg * KSEG;
    unsigned jw0, jw1, jw2, jw3;
    {
        int4 v0 = ((const int4*)wp)[0];
        int4 v1 = ((const int4*)wp)[1];
        int4 v2 = ((const int4*)wp)[2];
        int4 v3 = ((const int4*)wp)[3];
        #define CLP(x) ((unsigned)min(max((x), 0), NIDX - 1))
        jw0 = CLP(v0.x) | (CLP(v0.y) << 8) | (CLP(v0.z) << 16) | (CLP(v0.w) << 24);
        jw1 = CLP(v1.x) | (CLP(v1.y) << 8) | (CLP(v1.z) << 16) | (CLP(v1.w) << 24);
        jw2 = CLP(v2.x) | (CLP(v2.y) << 8) | (CLP(v2.z) << 16) | (CLP(v2.w) << 24);
        jw3 = CLP(v3.x) | (CLP(v3.y) << 8) | (CLP(v3.z) << 16) | (CLP(v3.w) << 24);
        #undef CLP
    }
    const unsigned lx = lane * 0x0101u;   // xor folded into bytes 0,1

    // ---- staging assignment: warp stages 2 rows (kk fixed, b0 and b0+1) per chunk ----
    const int kw = wid >> 4;              // kk within chunk: 0 or 1
    const int b0 = (wid & 15) * 2;
    const int b1 = b0 + 1;
    const int* ip0 = inp + (btile * BT + b0) * KDIM + seg * KSEG + kw;
    const int* ip1 = inp + (btile * BT + b1) * KDIM + seg * KSEG + kw;
    const uint32_t sm_base = (uint32_t)__cvta_generic_to_shared(S);
    const uint32_t sm0 = sm_base + ((kw * 32 + b0) * 256) * 4;
    const uint32_t sm1 = sm_base + ((kw * 32 + b1) * 256) * 4;

    float acc[32];
    #pragma unroll
    for (int i = 0; i < 32; ++i) acc[i] = 0.f;

    // ---- prologue: async-stage chunk 0 into buffer 0 ----
    {
        int r0 = min(max(ip0[0], 0), NIDX - 1);
        int r1 = min(max(ip1[0], 0), NIDX - 1);
        const float* s0 = lut + r0 * 256;
        const float* s1 = lut + r1 * 256;
        #pragma unroll
        for (int t = 0; t < 8; ++t) {
            int j = t * 32 + lane;
            cpa4(sm0 + ((unsigned)(j ^ b0) << 2), s0 + j);
            cpa4(sm1 + ((unsigned)(j ^ b1) << 2), s1 + j);
        }
        cp_commit();
        cp_wait0();
    }
    __syncthreads();

    // ---- pipelined chunks ----
    #pragma unroll 1
    for (int c = 0; c < NCH; ++c) {
        // async-stage next chunk into the other buffer (overlaps the gather)
        if (c < NCH - 1) {
            int r0 = min(max(ip0[(c + 1) * KCH], 0), NIDX - 1);
            int r1 = min(max(ip1[(c + 1) * KCH], 0), NIDX - 1);
            const float* s0 = lut + r0 * 256;
            const float* s1 = lut + r1 * 256;
            uint32_t d0 = sm0 + ((c + 1) & 1) * BUF_BYTES;
            uint32_t d1 = sm1 + ((c + 1) & 1) * BUF_BYTES;
            #pragma unroll
            for (int t = 0; t < 8; ++t) {
                int j = t * 32 + lane;
                cpa4(d0 + ((unsigned)(j ^ b0) << 2), s0 + j);
                cpa4(d1 + ((unsigned)(j ^ b1) << 2), s1 + j);
            }
            cp_commit();
        }

        // gather chunk c from buffer c&1 (conflict-free: lane == b)
        {
            const float* Sb = S + (c & 1) * BUF_F + lane * 256;
            unsigned word = (c < 2) ? jw0 : (c < 4) ? jw1 : (c < 6) ? jw2 : jw3;
            unsigned wv = word >> (16 * (c & 1));   // bytes 0,1 = the 2 kk's of chunk c
            #pragma unroll
            for (int oo = 0; oo < 32; ++oo) {
                unsigned w = __shfl_sync(0xffffffffu, wv, oo) ^ lx;
                acc[oo] += Sb[w & 255u];
                acc[oo] += Sb[8192 + ((w >> 8) & 255u)];
            }
        }

        if (c < NCH - 1) cp_wait0();
        __syncthreads();
    }

    // partial store: g_part[seg][obase+oo][btile*32+lane], coalesced over lane
    float* dst = &g_part[seg][obase][btile * BT + lane];
    #pragma unroll
    for (int oo = 0; oo < 32; ++oo)
        dst[oo * BATCH] = acc[oo];
}

// ---------------- epilogue: high-MLP transpose-reduce partials -> out[b][o] ----------------
// block: 32 o x 128 b tile; 1024 threads; warp w handles o = o0 + w.
__global__ __launch_bounds__(1024) void reduce_kernel(float* __restrict__ out) {
    __shared__ float tile[128 * 33];   // [b][o] with pitch 33 (conflict-free reads)
    const int o0 = blockIdx.x * 32;
    const int b0 = blockIdx.y * 128;
    const int l  = threadIdx.x & 31;
    const int w  = threadIdx.x >> 5;

    // 8 independent coalesced float4 loads (MLP=8)
    float4 a = make_float4(0.f, 0.f, 0.f, 0.f);
    #pragma unroll
    for (int s = 0; s < NSEG; ++s) {
        float4 v = *(const float4*)&g_part[s][o0 + w][b0 + 4 * l];
        a.x += v.x; a.y += v.y; a.z += v.z; a.w += v.w;
    }

    // scatter into [b][o] tile
    tile[(4 * l + 0) * 33 + w] = a.x;
    tile[(4 * l + 1) * 33 + w] = a.y;
    tile[(4 * l + 2) * 33 + w] = a.z;
    tile[(4 * l + 3) * 33 + w] = a.w;
    __syncthreads();

    // warp w writes b-rows {w, w+32, w+64, w+96}; lanes sweep o (coalesced)
    #pragma unroll
    for (int q = 0; q < 4; ++q) {
        int br = w + 32 * q;
        out[(b0 + br) * OUTF + o0 + l] = tile[br * 33 + l];
    }
}

// ---------------- launch ----------------
extern "C" void kernel_launch(void* const* d_in, const int* in_sizes, int n_in,
                              void* d_out, int out_size) {
    const int*   inp = (const int*)d_in[0];    // input_indices  [512,32,4]
    const int*   wgt = (const int*)d_in[1];    // weight_indices [1024,32,4]
    const float* lut = (const float*)d_in[2];  // lut_table [256,256]
    float* out = (float*)d_out;

    const int smem_bytes = 2 * BUF_F * (int)sizeof(float);  // 128 KB
    cudaFuncSetAttribute(lut_main, cudaFuncAttributeMaxDynamicSharedMemorySize, smem_bytes);
    dim3 grid(BATCH / BT, NSEG);
    lut_main<<<grid, MTHREADS, smem_bytes>>>(inp, wgt, lut);

    reduce_kernel<<<dim3(OUTF / 32, BATCH / 128), 1024>>>(out);
}

// round 6
// speedup vs baseline: 1.4631x; 1.4631x over previous
#include <cuda_runtime.h>
#include <cstdint>

// Problem constants
#define BATCH   512
#define OUTF    1024
#define KDIM    128      // NUM_BLOCKS * LATTICE_DIM
#define NIDX    256      // MAX_INDICES

// Tiling for main kernel
#define NSEG    8        // k-segments (grid.y)
#define KSEG    16       // k per segment
#define BT      32       // b per CTA (== warp width, conflict-free requirement)
#define MTHREADS 1024    // 32 warps: warp w owns o = w*32 .. w*32+31
#define BUF_F   (32 * 256)     // floats per buffer (1 k-slice, 32 b rows) = 8192 (32 KB)

// Per-segment partials, [seg][o][b] (b contiguous): 16 MB
__device__ float g_part[NSEG][OUTF][BATCH];

// ---------------- main kernel: register double-buffered conflict-free smem gather ----------------
// CTA (btile, seg): b in [btile*32, btile*32+32), k in [seg*16, seg*16+16), all 1024 o.
// smem: S[buf][b][ j ^ b ]; gather with lane==b is bank-conflict-free; staging STS
// (j = t*32+lane, fixed b=wid) is a lane permutation -> also conflict-free.
__global__ __launch_bounds__(MTHREADS, 1) void lut_main(
    const int*   __restrict__ inp,   // [BATCH, KDIM] int32
    const int*   __restrict__ wgt,   // [OUTF, KDIM]  int32
    const float* __restrict__ lut)   // [256, 256]
{
    extern __shared__ float S[];     // 2 * BUF_F floats = 64 KB

    const int btile = blockIdx.x;    // 0..15
    const int seg   = blockIdx.y;    // 0..7
    const int tid   = threadIdx.x;
    const int wid   = tid >> 5;
    const int lane  = tid & 31;
    const int obase = wid * 32;

    // ---- fused pack: this lane's 16 weight indices (o = obase+lane) as 4 byte-words ----
    const int* wp = wgt + (obase + lane) * KDIM + seg * KSEG;
    unsigned jw0, jw1, jw2, jw3;
    {
        int4 v0 = ((const int4*)wp)[0];
        int4 v1 = ((const int4*)wp)[1];
        int4 v2 = ((const int4*)wp)[2];
        int4 v3 = ((const int4*)wp)[3];
        #define CLP(x) ((unsigned)min(max((x), 0), NIDX - 1))
        jw0 = CLP(v0.x) | (CLP(v0.y) << 8) | (CLP(v0.z) << 16) | (CLP(v0.w) << 24);
        jw1 = CLP(v1.x) | (CLP(v1.y) << 8) | (CLP(v1.z) << 16) | (CLP(v1.w) << 24);
        jw2 = CLP(v2.x) | (CLP(v2.y) << 8) | (CLP(v2.z) << 16) | (CLP(v2.w) << 24);
        jw3 = CLP(v3.x) | (CLP(v3.y) << 8) | (CLP(v3.z) << 16) | (CLP(v3.w) << 24);
        #undef CLP
    }

    // ---- staging: warp stages the single row for b == wid each chunk ----
    const int* ip = inp + (btile * BT + wid) * KDIM + seg * KSEG;
    float* drow0 = S + wid * 256;            // buffer 0 row base (this warp's b)
    const float* Sl0 = S + lane * 256;       // buffer 0 gather base (lane == b)

    float acc[32];
    #pragma unroll
    for (int i = 0; i < 32; ++i) acc[i] = 0.f;

    // ---- prologue: stage k-slice 0 into buffer 0 ----
    {
        int r = min(max(ip[0], 0), NIDX - 1);
        const float* src = lut + r * 256;
        #pragma unroll
        for (int t = 0; t < 8; ++t) {
            int j = t * 32 + lane;
            drow0[j ^ wid] = __ldg(src + j);
        }
    }
    __syncthreads();

    // ---- pipelined k-slices (16 of them, one per chunk) ----
    #pragma unroll 1
    for (int c = 0; c < KSEG; ++c) {
        // LDG next slice into registers (latency hides under the gather)
        float rg[8];
        if (c < KSEG - 1) {
            int r = min(max(ip[c + 1], 0), NIDX - 1);
            const float* src = lut + r * 256;
            #pragma unroll
            for (int t = 0; t < 8; ++t)
                rg[t] = __ldg(src + t * 32 + lane);
        }

        // gather slice c from buffer c&1 (conflict-free: lane == b)
        {
            const float* Sb = Sl0 + (c & 1) * BUF_F;
            unsigned word = (c < 4) ? jw0 : (c < 8) ? jw1 : (c < 12) ? jw2 : jw3;
            unsigned wv8 = (word >> (8 * (c & 3))) & 255u;   // pre-extract my o's byte
            #pragma unroll
            for (int oo = 0; oo < 32; ++oo) {
                unsigned j = __shfl_sync(0xffffffffu, wv8, oo) ^ (unsigned)lane;
                acc[oo] += Sb[j];
            }
        }

        // STS next slice into the other buffer (conflict-free permutation)
        if (c < KSEG - 1) {
            float* d = drow0 + ((c + 1) & 1) * BUF_F;
            #pragma unroll
            for (int t = 0; t < 8; ++t)
                d[(t * 32 + lane) ^ wid] = rg[t];
        }
        __syncthreads();
    }

    // partial store: g_part[seg][obase+oo][btile*32+lane], coalesced over lane
    float* dst = &g_part[seg][obase][btile * BT + lane];
    #pragma unroll
    for (int oo = 0; oo < 32; ++oo)
        dst[oo * BATCH] = acc[oo];
}

// ---------------- epilogue: high-occupancy transpose-reduce partials -> out[b][o] ----------------
// 512 blocks x 256 threads; block tile = 32 o x 32 b; thread = 1 o x 4 b (float4), MLP=8.
__global__ __launch_bounds__(256) void reduce_kernel(float* __restrict__ out) {
    __shared__ float tile[32 * 33];    // [b][o], pitch 33
    const int o0 = blockIdx.x * 32;
    const int b0 = blockIdx.y * 32;
    const int t  = threadIdx.x;
    const int oi = t >> 3;             // 0..31
    const int bq = t & 7;              // 0..7  -> b offset bq*4

    float4 a = make_float4(0.f, 0.f, 0.f, 0.f);
    #pragma unroll
    for (int s = 0; s < NSEG; ++s) {   // 8 independent coalesced float4 loads
        float4 v = *(const float4*)&g_part[s][o0 + oi][b0 + 4 * bq];
        a.x += v.x; a.y += v.y; a.z += v.z; a.w += v.w;
    }
    tile[(4 * bq + 0) * 33 + oi] = a.x;
    tile[(4 * bq + 1) * 33 + oi] = a.y;
    tile[(4 * bq + 2) * 33 + oi] = a.z;
    tile[(4 * bq + 3) * 33 + oi] = a.w;
    __syncthreads();

    const int l  = t & 31;             // o offset (coalesced writes)
    const int br = t >> 5;             // 0..7
    #pragma unroll
    for (int q = 0; q < 4; ++q) {
        int b = br + 8 * q;
        out[(b0 + b) * OUTF + o0 + l] = tile[b * 33 + l];
    }
}

// ---------------- launch ----------------
extern "C" void kernel_launch(void* const* d_in, const int* in_sizes, int n_in,
                              void* d_out, int out_size) {
    const int*   inp = (const int*)d_in[0];    // input_indices  [512,32,4]
    const int*   wgt = (const int*)d_in[1];    // weight_indices [1024,32,4]
    const float* lut = (const float*)d_in[2];  // lut_table [256,256]
    float* out = (float*)d_out;

    const int smem_bytes = 2 * BUF_F * (int)sizeof(float);  // 64 KB
    cudaFuncSetAttribute(lut_main, cudaFuncAttributeMaxDynamicSharedMemorySize, smem_bytes);
    dim3 grid(BATCH / BT, NSEG);
    lut_main<<<grid, MTHREADS, smem_bytes>>>(inp, wgt, lut);

    reduce_kernel<<<dim3(OUTF / 32, BATCH / 32), 256>>>(out);
}

// round 9
// speedup vs baseline: 1.6769x; 1.1462x over previous
#include <cuda_runtime.h>
#include <cstdint>

// Problem constants
#define BATCH   512
#define OUTF    1024
#define KDIM    128      // NUM_BLOCKS * LATTICE_DIM
#define NIDX    256      // MAX_INDICES

// Tiling for main kernel
#define NSEG    8        // k-segments (grid.y)
#define KSEG    16       // k per segment
#define KCH     2        // k per staging chunk (per buffer)
#define NCH     (KSEG / KCH)       // 8 chunks
#define BT      32       // b per CTA (== warp width, conflict-free requirement)
#define MTHREADS 1024    // 32 warps: warp w owns o = w*32 .. w*32+31
#define BUF_F   (KCH * 32 * 256)   // floats per buffer = 16384 (64 KB)

// Per-segment partials, [seg][o][b] (b contiguous): 16 MB
__device__ float g_part[NSEG][OUTF][BATCH];

// ---------------- main kernel: double-buffered conflict-free smem gather ----------------
// CTA (btile, seg): b in [btile*32, btile*32+32), k in [seg*16, seg*16+16), all 1024 o.
// smem: S[buf][kk][b][ j ^ b ]; gather with lane==b is bank-conflict-free; staging STS
// (j = t*32+lane, fixed b) is a lane permutation -> also conflict-free.
__global__ __launch_bounds__(MTHREADS, 1) void lut_main(
    const int*   __restrict__ inp,   // [BATCH, KDIM] int32
    const int*   __restrict__ wgt,   // [OUTF, KDIM]  int32
    const float* __restrict__ lut)   // [256, 256]
{
    extern __shared__ float S[];     // 2 * BUF_F floats = 128 KB

    const int btile = blockIdx.x;    // 0..15
    const int seg   = blockIdx.y;    // 0..7
    const int tid   = threadIdx.x;
    const int wid   = tid >> 5;
    const int lane  = tid & 31;
    const int obase = wid * 32;

    // ---- fused pack: this lane's 16 weight indices (o = obase+lane) as 4 byte-words ----
    const int* wp = wgt + (obase + lane) * KDIM + seg * KSEG;
    unsigned jw0, jw1, jw2, jw3;
    {
        int4 v0 = ((const int4*)wp)[0];
        int4 v1 = ((const int4*)wp)[1];
        int4 v2 = ((const int4*)wp)[2];
        int4 v3 = ((const int4*)wp)[3];
        #define CLP(x) ((unsigned)min(max((x), 0), NIDX - 1))
        jw0 = CLP(v0.x) | (CLP(v0.y) << 8) | (CLP(v0.z) << 16) | (CLP(v0.w) << 24);
        jw1 = CLP(v1.x) | (CLP(v1.y) << 8) | (CLP(v1.z) << 16) | (CLP(v1.w) << 24);
        jw2 = CLP(v2.x) | (CLP(v2.y) << 8) | (CLP(v2.z) << 16) | (CLP(v2.w) << 24);
        jw3 = CLP(v3.x) | (CLP(v3.y) << 8) | (CLP(v3.z) << 16) | (CLP(v3.w) << 24);
        #undef CLP
    }
    const unsigned lx = lane * 0x0101u;   // xor folded into bytes 0,1

    // ---- staging assignment: warp stages 2 rows (kk fixed, b0 and b0+1) per chunk ----
    const int kw = wid >> 4;              // kk within chunk: 0 or 1
    const int b0 = (wid & 15) * 2;
    const int b1 = b0 + 1;
    const int* ip0 = inp + (btile * BT + b0) * KDIM + seg * KSEG + kw;
    const int* ip1 = inp + (btile * BT + b1) * KDIM + seg * KSEG + kw;
    float* drow0base = S + (kw * 32 + b0) * 256;   // + buf*BUF_F at use
    float* drow1base = S + (kw * 32 + b1) * 256;

    float acc[32];
    #pragma unroll
    for (int i = 0; i < 32; ++i) acc[i] = 0.f;

    // ---- prologue: stage chunk 0 into buffer 0 ----
    {
        int r0 = min(max(ip0[0], 0), NIDX - 1);
        int r1 = min(max(ip1[0], 0), NIDX - 1);
        const float* s0 = lut + r0 * 256;
        const float* s1 = lut + r1 * 256;
        #pragma unroll
        for (int t = 0; t < 8; ++t) {
            int j = t * 32 + lane;
            drow0base[j ^ b0] = __ldg(s0 + j);
            drow1base[j ^ b1] = __ldg(s1 + j);
        }
    }
    __syncthreads();

    // ---- pipelined chunks (split staging: 8 staging regs reused for rows A and B) ----
    #pragma unroll 1
    for (int c = 0; c < NCH; ++c) {
        const bool more = (c < NCH - 1);
        const float* sA = lut;
        const float* sB = lut;
        if (more) {
            int r0 = min(max(ip0[(c + 1) * KCH], 0), NIDX - 1);
            int r1 = min(max(ip1[(c + 1) * KCH], 0), NIDX - 1);
            sA = lut + r0 * 256;
            sB = lut + r1 * 256;
        }

        const float* Sb = S + (c & 1) * BUF_F + lane * 256;
        unsigned word = (c < 2) ? jw0 : (c < 4) ? jw1 : (c < 6) ? jw2 : jw3;
        unsigned wv = word >> (16 * (c & 1));   // bytes 0,1 = the 2 kk's of chunk c

        float rg[8];
        // LDG row A (latency hides under first gather half)
        if (more) {
            #pragma unroll
            for (int t = 0; t < 8; ++t) rg[t] = __ldg(sA + t * 32 + lane);
        }

        // gather oo = 0..15
        #pragma unroll
        for (int oo = 0; oo < 16; ++oo) {
            unsigned w = __shfl_sync(0xffffffffu, wv, oo) ^ lx;
            acc[oo] += Sb[w & 255u];
            acc[oo] += Sb[8192 + ((w >> 8) & 255u)];
        }

        if (more) {
            // STS row A, then LDG row B into the same registers
            float* dA = drow0base + ((c + 1) & 1) * BUF_F;
            #pragma unroll
            for (int t = 0; t < 8; ++t) dA[(t * 32 + lane) ^ b0] = rg[t];
            #pragma unroll
            for (int t = 0; t < 8; ++t) rg[t] = __ldg(sB + t * 32 + lane);
        }

        // gather oo = 16..31 (covers LDG row B latency)
        #pragma unroll
        for (int oo = 16; oo < 32; ++oo) {
            unsigned w = __shfl_sync(0xffffffffu, wv, oo) ^ lx;
            acc[oo] += Sb[w & 255u];
            acc[oo] += Sb[8192 + ((w >> 8) & 255u)];
        }

        if (more) {
            float* dB = drow1base + ((c + 1) & 1) * BUF_F;
            #pragma unroll
            for (int t = 0; t < 8; ++t) dB[(t * 32 + lane) ^ b1] = rg[t];
        }
        __syncthreads();
    }

    // partial store: g_part[seg][obase+oo][btile*32+lane], coalesced over lane
    float* dst = &g_part[seg][obase][btile * BT + lane];
    #pragma unroll
    for (int oo = 0; oo < 32; ++oo)
        dst[oo * BATCH] = acc[oo];
}

// ---------------- epilogue: high-grid transpose-reduce partials -> out[b][o] ----------------
// 1024 blocks x 128 threads; block tile = 16 o x 32 b; thread: 1 o x 4 b (float4), MLP=8.
__global__ __launch_bounds__(128) void reduce_kernel(float* __restrict__ out) {
    __shared__ float tile[32 * 17];    // [b][o], pitch 17 (conflict-free both phases)
    const int o0 = blockIdx.x * 16;
    const int b0 = blockIdx.y * 32;
    const int t  = threadIdx.x;
    const int oi = t >> 3;             // 0..15
    const int bq = t & 7;              // 0..7  -> b offset bq*4

    float4 a = make_float4(0.f, 0.f, 0.f, 0.f);
    #pragma unroll
    for (int s = 0; s < NSEG; ++s) {   // 8 independent coalesced float4 loads
        float4 v = *(const float4*)&g_part[s][o0 + oi][b0 + 4 * bq];
        a.x += v.x; a.y += v.y; a.z += v.z; a.w += v.w;
    }
    tile[(4 * bq + 0) * 17 + oi] = a.x;
    tile[(4 * bq + 1) * 17 + oi] = a.y;
    tile[(4 * bq + 2) * 17 + oi] = a.z;
    tile[(4 * bq + 3) * 17 + oi] = a.w;
    __syncthreads();

    const int l  = t & 15;             // o offset (contiguous 64B runs)
    const int br = t >> 4;             // 0..7
    #pragma unroll
    for (int q = 0; q < 4; ++q) {
        int b = br + 8 * q;
        out[(b0 + b) * OUTF + o0 + l] = tile[b * 17 + l];
    }
}

// ---------------- launch ----------------
extern "C" void kernel_launch(void* const* d_in, const int* in_sizes, int n_in,
                              void* d_out, int out_size) {
    const int*   inp = (const int*)d_in[0];    // input_indices  [512,32,4]
    const int*   wgt = (const int*)d_in[1];    // weight_indices [1024,32,4]
    const float* lut = (const float*)d_in[2];  // lut_table [256,256]
    float* out = (float*)d_out;

    const int smem_bytes = 2 * BUF_F * (int)sizeof(float);  // 128 KB
    cudaFuncSetAttribute(lut_main, cudaFuncAttributeMaxDynamicSharedMemorySize, smem_bytes);
    dim3 grid(BATCH / BT, NSEG);
    lut_main<<<grid, MTHREADS, smem_bytes>>>(inp, wgt, lut);

    reduce_kernel<<<dim3(OUTF / 16, BATCH / 32), 128>>>(out);
}